// round 1
// baseline (speedup 1.0000x reference)
#include <cuda_runtime.h>
#include <cuda_bf16.h>
#include <cstdint>

#define N_NODES 100000
#define E_EDGES 1600000
#define ET_EDGES (E_EDGES + N_NODES)   // with self loops
#define IN_CH 64
#define HID 16
#define HEADS 4
#define G_GRAPHS 512
#define NB_SCAN ((N_NODES + 255) / 256)  // 391

// ---------------- scratch (device globals; no runtime allocation) ----------
__device__ int   g_hist[N_NODES];
__device__ int   g_scan[N_NODES];
__device__ int   g_bsum[NB_SCAN];
__device__ int   g_offs[N_NODES + 1];
__device__ int   g_cursor[N_NODES];
__device__ int   g_ssrc[ET_EDGES];

__device__ float g_h1 [N_NODES * 64];
__device__ float g_h1e[N_NODES * 64];
__device__ float g_als1[N_NODES * 4];
__device__ float g_ald1[N_NODES * 4];
__device__ float g_h2 [N_NODES * 16];
__device__ float g_al2s[N_NODES];
__device__ float g_al2d[N_NODES];
__device__ float g_pool[G_GRAPHS * 16];
__device__ float g_cnt [G_GRAPHS];
__device__ int   g_is64;

// ---------------- helpers ----------------
__device__ __forceinline__ int edge_src(const void* p, int i) {
    if (i >= E_EDGES) return i - E_EDGES;              // self loop
    return g_is64 ? (int)((const long long*)p)[i] : ((const int*)p)[i];
}
__device__ __forceinline__ int edge_dst(const void* p, int i) {
    if (i >= E_EDGES) return i - E_EDGES;              // self loop
    return g_is64 ? (int)((const long long*)p)[E_EDGES + i]
                  : ((const int*)p)[E_EDGES + i];
}

// ---------------- K0: init + dtype detect ----------------
__global__ void k_init(const unsigned* ei) {
    int i = blockIdx.x * blockDim.x + threadIdx.x;
    if (i < N_NODES) g_hist[i] = 0;
    if (i < G_GRAPHS * 16) g_pool[i] = 0.f;
    if (i < G_GRAPHS) g_cnt[i] = 0.f;
    if (i == 0) {
        // if data is int64, every odd 32-bit word (high half) is 0 (values < 2^31).
        int is64 = 1;
        #pragma unroll
        for (int k = 1; k < 64; k += 2) if (ei[k] != 0u) is64 = 0;
        g_is64 = is64;
    }
}

// ---------------- K1: histogram of dst ----------------
__global__ void k_hist(const void* ei) {
    int i = blockIdx.x * blockDim.x + threadIdx.x;
    if (i >= ET_EDGES) return;
    atomicAdd(&g_hist[edge_dst(ei, i)], 1);
}

// ---------------- K2: scan (3 kernels) ----------------
__global__ void k_scan1() {
    __shared__ int sh[256];
    int i = blockIdx.x * 256 + threadIdx.x;
    int v = (i < N_NODES) ? g_hist[i] : 0;
    sh[threadIdx.x] = v;
    __syncthreads();
    for (int off = 1; off < 256; off <<= 1) {
        int t = (threadIdx.x >= off) ? sh[threadIdx.x - off] : 0;
        __syncthreads();
        sh[threadIdx.x] += t;
        __syncthreads();
    }
    if (i < N_NODES) g_scan[i] = sh[threadIdx.x];
    if (threadIdx.x == 255) g_bsum[blockIdx.x] = sh[255];
}

__global__ void k_scan2() {
    __shared__ int sh[512];
    int t = threadIdx.x;
    sh[t] = (t < NB_SCAN) ? g_bsum[t] : 0;
    __syncthreads();
    for (int off = 1; off < 512; off <<= 1) {
        int v = (t >= off) ? sh[t - off] : 0;
        __syncthreads();
        sh[t] += v;
        __syncthreads();
    }
    if (t < NB_SCAN) g_bsum[t] = sh[t];   // inclusive
}

__global__ void k_scan3() {
    int i = blockIdx.x * 256 + threadIdx.x;
    if (i >= N_NODES) return;
    int b = blockIdx.x;
    int base = (b == 0) ? 0 : g_bsum[b - 1];
    int incl = base + g_scan[i];
    int excl = incl - g_hist[i];
    g_offs[i] = excl;
    g_cursor[i] = excl;
    if (i == N_NODES - 1) g_offs[N_NODES] = incl;
}

// ---------------- K3: scatter edges sorted by dst ----------------
__global__ void k_scatter(const void* ei) {
    int i = blockIdx.x * blockDim.x + threadIdx.x;
    if (i >= ET_EDGES) return;
    int dst = edge_dst(ei, i);
    int src = edge_src(ei, i);
    int pos = atomicAdd(&g_cursor[dst], 1);
    g_ssrc[pos] = src;
}

// ---------------- K4: GEMM1 h1 = x @ W1, attention logits ----------------
__global__ __launch_bounds__(128) void k_gemm1(
    const float* __restrict__ x, const float* __restrict__ W1,
    const float* __restrict__ a1s, const float* __restrict__ a1d) {
    __shared__ float ws[64 * 64];
    __shared__ float sas[64], sad[64];
    for (int i = threadIdx.x; i < 4096; i += 128) ws[i] = W1[i];
    if (threadIdx.x < 64) { sas[threadIdx.x] = a1s[threadIdx.x]; sad[threadIdx.x] = a1d[threadIdx.x]; }
    __syncthreads();
    int n = blockIdx.x * 128 + threadIdx.x;
    if (n >= N_NODES) return;

    float xr[64];
    const float4* xp = (const float4*)(x + (size_t)n * 64);
    #pragma unroll
    for (int i = 0; i < 16; i++) {
        float4 v = xp[i];
        xr[4*i] = v.x; xr[4*i+1] = v.y; xr[4*i+2] = v.z; xr[4*i+3] = v.w;
    }
    #pragma unroll 1
    for (int h = 0; h < 4; h++) {
        float acc[16];
        #pragma unroll
        for (int j = 0; j < 16; j++) acc[j] = 0.f;
        #pragma unroll
        for (int k = 0; k < 64; k++) {
            float xv = xr[k];
            #pragma unroll
            for (int j = 0; j < 16; j++)
                acc[j] = fmaf(xv, ws[k * 64 + h * 16 + j], acc[j]);
        }
        float s = 0.f, d = 0.f;
        #pragma unroll
        for (int j = 0; j < 16; j++) {
            s = fmaf(acc[j], sas[h * 16 + j], s);
            d = fmaf(acc[j], sad[h * 16 + j], d);
        }
        float4* hp = (float4*)(g_h1 + (size_t)n * 64 + h * 16);
        hp[0] = make_float4(acc[0], acc[1], acc[2], acc[3]);
        hp[1] = make_float4(acc[4], acc[5], acc[6], acc[7]);
        hp[2] = make_float4(acc[8], acc[9], acc[10], acc[11]);
        hp[3] = make_float4(acc[12], acc[13], acc[14], acc[15]);
        g_als1[n * 4 + h] = s;
        g_ald1[n * 4 + h] = d;
    }
}

// ---------------- K5: layer-1 aggregation, warp per dst ----------------
__global__ __launch_bounds__(256) void k_agg1(const float* __restrict__ b1) {
    int wid = (blockIdx.x * blockDim.x + threadIdx.x) >> 5;
    int lane = threadIdx.x & 31;
    if (wid >= N_NODES) return;
    int dst = wid;
    int start = g_offs[dst];
    int end   = g_offs[dst + 1];
    int hh = lane >> 3;                       // head of channels (2*lane, 2*lane+1)
    float aldv = g_ald1[dst * 4 + hh];
    float ax = 0.f, ay = 0.f, wsum = 0.f;
    for (int k = start; k < end; k++) {
        int src = g_ssrc[k];
        float e = g_als1[src * 4 + hh] + aldv;
        e = e > 0.f ? e : 0.2f * e;
        float w = __expf(e);
        float2 v = *(const float2*)(g_h1 + (size_t)src * 64 + 2 * lane);
        ax = fmaf(w, v.x, ax);
        ay = fmaf(w, v.y, ay);
        wsum += w;
    }
    float inv = 1.0f / wsum;                  // self-loop guarantees wsum > 0
    float o0 = ax * inv + b1[2 * lane];
    float o1 = ay * inv + b1[2 * lane + 1];
    o0 = o0 > 0.f ? o0 : (__expf(o0) - 1.f);  // ELU
    o1 = o1 > 0.f ? o1 : (__expf(o1) - 1.f);
    *(float2*)(g_h1e + (size_t)dst * 64 + 2 * lane) = make_float2(o0, o1);
}

// ---------------- K6: GEMM2 h2 = h1e @ W2, layer-2 logits ----------------
__global__ __launch_bounds__(128) void k_gemm2(
    const float* __restrict__ W2,
    const float* __restrict__ a2s, const float* __restrict__ a2d) {
    __shared__ float ws[64 * 16];
    __shared__ float s2s[16], s2d[16];
    for (int i = threadIdx.x; i < 1024; i += 128) ws[i] = W2[i];
    if (threadIdx.x < 16) { s2s[threadIdx.x] = a2s[threadIdx.x]; s2d[threadIdx.x] = a2d[threadIdx.x]; }
    __syncthreads();
    int n = blockIdx.x * 128 + threadIdx.x;
    if (n >= N_NODES) return;

    float v[64];
    const float4* vp = (const float4*)(g_h1e + (size_t)n * 64);
    #pragma unroll
    for (int i = 0; i < 16; i++) {
        float4 t = vp[i];
        v[4*i] = t.x; v[4*i+1] = t.y; v[4*i+2] = t.z; v[4*i+3] = t.w;
    }
    float acc[16];
    #pragma unroll
    for (int j = 0; j < 16; j++) acc[j] = 0.f;
    #pragma unroll
    for (int k = 0; k < 64; k++) {
        float xv = v[k];
        #pragma unroll
        for (int j = 0; j < 16; j++)
            acc[j] = fmaf(xv, ws[k * 16 + j], acc[j]);
    }
    float s = 0.f, d = 0.f;
    #pragma unroll
    for (int j = 0; j < 16; j++) {
        s = fmaf(acc[j], s2s[j], s);
        d = fmaf(acc[j], s2d[j], d);
    }
    float4* hp = (float4*)(g_h2 + (size_t)n * 16);
    hp[0] = make_float4(acc[0], acc[1], acc[2], acc[3]);
    hp[1] = make_float4(acc[4], acc[5], acc[6], acc[7]);
    hp[2] = make_float4(acc[8], acc[9], acc[10], acc[11]);
    hp[3] = make_float4(acc[12], acc[13], acc[14], acc[15]);
    g_al2s[n] = s;
    g_al2d[n] = d;
}

// ---------------- K7: layer-2 aggregation + pooling, half-warp per dst ----
__global__ __launch_bounds__(256) void k_agg2(
    const float* __restrict__ b2, const void* __restrict__ batchp) {
    int hw = (blockIdx.x * blockDim.x + threadIdx.x) >> 4;
    int c = threadIdx.x & 15;
    if (hw >= N_NODES) return;
    int dst = hw;
    int start = g_offs[dst];
    int end   = g_offs[dst + 1];
    float aldv = g_al2d[dst];
    float acc = 0.f, wsum = 0.f;
    for (int k = start; k < end; k++) {
        int src = g_ssrc[k];
        float e = g_al2s[src] + aldv;
        e = e > 0.f ? e : 0.2f * e;
        float w = __expf(e);
        acc = fmaf(w, g_h2[(size_t)src * 16 + c], acc);
        wsum += w;
    }
    float o = acc / wsum + b2[c];
    o = o > 0.f ? o : (__expf(o) - 1.f);      // ELU
    int g = g_is64 ? (int)((const long long*)batchp)[dst]
                   : ((const int*)batchp)[dst];
    atomicAdd(&g_pool[g * 16 + c], o);
    if (c == 0) atomicAdd(&g_cnt[g], 1.0f);
}

// ---------------- K8: final mean + linear head ----------------
__global__ void k_final(const float* __restrict__ Wc, const float* __restrict__ bc,
                        float* __restrict__ out) {
    int g = threadIdx.x;
    if (g >= G_GRAPHS) return;
    float inv = 1.0f / fmaxf(g_cnt[g], 1.0f);
    float s = 0.f;
    #pragma unroll
    for (int c = 0; c < 16; c++)
        s = fmaf(g_pool[g * 16 + c] * inv, Wc[c], s);
    out[g] = s + bc[0];
}

// ---------------- launch ----------------
extern "C" void kernel_launch(void* const* d_in, const int* in_sizes, int n_in,
                              void* d_out, int out_size) {
    const float* x    = (const float*)d_in[0];
    const void*  ei   = d_in[1];
    const void*  batch = d_in[2];
    const float* W1   = (const float*)d_in[3];
    const float* a1s  = (const float*)d_in[4];
    const float* a1d  = (const float*)d_in[5];
    const float* b1   = (const float*)d_in[6];
    const float* W2   = (const float*)d_in[7];
    const float* a2s  = (const float*)d_in[8];
    const float* a2d  = (const float*)d_in[9];
    const float* b2   = (const float*)d_in[10];
    const float* Wc   = (const float*)d_in[11];
    const float* bc   = (const float*)d_in[12];
    float* out = (float*)d_out;

    k_init<<<(N_NODES + 255) / 256, 256>>>((const unsigned*)ei);
    k_hist<<<(ET_EDGES + 255) / 256, 256>>>(ei);
    k_scan1<<<NB_SCAN, 256>>>();
    k_scan2<<<1, 512>>>();
    k_scan3<<<NB_SCAN, 256>>>();
    k_scatter<<<(ET_EDGES + 255) / 256, 256>>>(ei);
    k_gemm1<<<(N_NODES + 127) / 128, 128>>>(x, W1, a1s, a1d);
    k_agg1<<<(N_NODES * 32 + 255) / 256, 256>>>(b1);
    k_gemm2<<<(N_NODES + 127) / 128, 128>>>(W2, a2s, a2d);
    k_agg2<<<(N_NODES * 16 + 255) / 256, 256>>>(b2, batch);
    k_final<<<1, 512>>>(Wc, bc, out);
}